// round 6
// baseline (speedup 1.0000x reference)
#include <cuda_runtime.h>
#include <cuda_bf16.h>
#include <cstdint>

#define LAMBDA_COORD 5.0f
#define LAMBDA_NOOBJ 0.5f
#define EPS 1e-9f
#define WPB 8                 // warps per block
#define BPSM 4                // blocks per SM
#define NBLK (148 * BPSM)     // one resident wave = 592 blocks
#define SLAB_FLOATS 512       // 8*8*8 floats per batch

__device__ double g_partial[NBLK];
__device__ unsigned g_count = 0;

__device__ __forceinline__ float bbox_iou(float px, float py, float pr,
                                          float gx, float gy, float gr) {
    float l1 = px - pr, r1 = px + pr, t1 = py - pr, b1 = py + pr;
    float l2 = gx - gr, r2 = gx + gr, t2 = gy - gr, b2 = gy + gr;
    float iw = fmaxf(fminf(r1, r2) - fmaxf(l1, l2), 0.0f);
    float ih = fmaxf(fminf(b1, b2) - fmaxf(t1, t2), 0.0f);
    float inter = iw * ih;
    float a1 = (r1 - l1) * (b1 - t1);
    float a2 = (r2 - l2) * (b2 - t2);
    return inter / (a1 + a2 - inter + EPS);
}

__global__ void __launch_bounds__(WPB * 32, BPSM)
yolo_loss_kernel(const float* __restrict__ pred,
                 const int*   __restrict__ label_rc,
                 const float* __restrict__ label_box,
                 int B, float* __restrict__ out) {
    // Dynamic smem: WPB * 2KB gather regions = 16 KB. No static shared;
    // the post-loop reduction aliases into this buffer.
    extern __shared__ float dsh[];

    const int warp = threadIdx.x >> 5;
    const int lane = threadIdx.x & 31;
    const int NW = NBLK * WPB;
    const int b0 = blockIdx.x * WPB + warp;

    float4* shw4 = reinterpret_cast<float4*>(dsh + warp * SLAB_FLOATS);

    float acc = 0.0f;

    // this lane owns f4 indices: lane, lane+32, lane+64, lane+96
    // f4 index j covers cell j>>1 (even j -> ch0..3, odd j -> ch4..7)

    // ---- prefetch first batch: pred slab to regs + labels ----
    float4 c0, c1, c2, c3;
    if (b0 < B) {
        const float4* p4 = reinterpret_cast<const float4*>(pred + (size_t)b0 * SLAB_FLOATS);
        c0 = p4[lane]; c1 = p4[lane + 32]; c2 = p4[lane + 64]; c3 = p4[lane + 96];
    }
    int2 nrc = make_int2(0, 0);
    float ngx = 0.f, ngy = 0.f, ngr = 0.f;
    if (lane < 16 && b0 < B) {
        nrc = reinterpret_cast<const int2*>(label_rc)[(size_t)b0 * 16 + lane];
        const float* bx = label_box + ((size_t)b0 * 16 + lane) * 3;
        ngx = bx[0]; ngy = bx[1]; ngr = bx[2];
    }

    for (int b = b0; b < B; b += NW) {
        const int bn = b + NW;

        // ---- issue next batch's global loads first (independent chain) ----
        float4 n0, n1, n2, n3;
        if (bn < B) {
            const float4* p4 = reinterpret_cast<const float4*>(pred + (size_t)bn * SLAB_FLOATS);
            n0 = p4[lane]; n1 = p4[lane + 32]; n2 = p4[lane + 64]; n3 = p4[lane + 96];
        }

        // current labels
        int2 rc = nrc;
        float gx = ngx, gy = ngy, gr = ngr;

        // prefetch next batch's labels
        if (lane < 16 && bn < B) {
            nrc = reinterpret_cast<const int2*>(label_rc)[(size_t)bn * 16 + lane];
            const float* bx = label_box + ((size_t)bn * 16 + lane) * 3;
            ngx = bx[0]; ngy = bx[1]; ngr = bx[2];
        }

        // occupancy bitmask over 64 cells (duplicates collapse)
        unsigned mlo = 0, mhi = 0;
        int cell_idx = 0;
        if (lane < 16) {
            cell_idx = rc.x * 8 + rc.y;
            if (cell_idx < 32) mlo = 1u << cell_idx;
            else               mhi = 1u << (cell_idx - 32);
        }
        mlo = __reduce_or_sync(0xffffffffu, mlo);
        mhi = __reduce_or_sync(0xffffffffu, mhi);

        // ---- noobj from registers + stash object f4s to smem ----
        // cell of f4 index j = j>>1; obj test against mask
        {
            int cell = lane >> 1;  // j = lane (cells 0..15)
            bool obj = (mlo >> cell) & 1u;
            if (obj) shw4[lane] = c0;
            else     acc += LAMBDA_NOOBJ * c0.w * c0.w;
        }
        {
            int cell = (lane + 32) >> 1;  // cells 16..31
            bool obj = (mlo >> cell) & 1u;
            if (obj) shw4[lane + 32] = c1;
            else     acc += LAMBDA_NOOBJ * c1.w * c1.w;
        }
        {
            int cell = (lane + 64) >> 1;  // cells 32..47
            bool obj = (mhi >> (cell - 32)) & 1u;
            if (obj) shw4[lane + 64] = c2;
            else     acc += LAMBDA_NOOBJ * c2.w * c2.w;
        }
        {
            int cell = (lane + 96) >> 1;  // cells 48..63
            bool obj = (mhi >> (cell - 32)) & 1u;
            if (obj) shw4[lane + 96] = c3;
            else     acc += LAMBDA_NOOBJ * c3.w * c3.w;
        }
        __syncwarp();

        // ---- per-label coord + conf losses (lanes 0..15) ----
        if (lane < 16) {
            float4 a = shw4[cell_idx * 2];       // p0..p3
            float4 c = shw4[cell_idx * 2 + 1];   // q0..q3

            float iou1 = bbox_iou(a.x, a.y, a.z, gx, gy, gr);
            float iou2 = bbox_iou(c.x, c.y, c.z, gx, gy, gr);
            bool swp = iou2 > iou1;

            float cx   = swp ? c.x : a.x;
            float cy   = swp ? c.y : a.y;
            float cr   = swp ? c.z : a.z;
            float conf = swp ? c.w : a.w;
            float ucnf = swp ? a.w : c.w;
            float big  = swp ? iou2 : iou1;
            float sml  = swp ? iou1 : iou2;

            float dx = cx - gx, dy = cy - gy, dr = cr - gr;
            acc += LAMBDA_COORD * (dx * dx + dy * dy + dr * dr);
            float dc = big - conf;
            acc += dc * dc;
            float du = sml - ucnf;
            acc += LAMBDA_NOOBJ * du * du;
        }
        __syncwarp();  // protect smem gather region before next iter's STS

        c0 = n0; c1 = n1; c2 = n2; c3 = n3;
    }

    __syncthreads();  // all warps done before aliasing dsh as reduction scratch

    double* blocksum = reinterpret_cast<double*>(dsh);        // 8 doubles
    int*    islast_p = reinterpret_cast<int*>(dsh + 16);      // 1 int
    double* red      = reinterpret_cast<double*>(dsh + 32);   // 256 doubles

    // warp reduce
#pragma unroll
    for (int o = 16; o > 0; o >>= 1)
        acc += __shfl_xor_sync(0xffffffffu, acc, o);
    if (lane == 0) blocksum[warp] = (double)acc;
    __syncthreads();

    if (threadIdx.x == 0) {
        double s = 0.0;
#pragma unroll
        for (int w = 0; w < WPB; w++) s += blocksum[w];
        g_partial[blockIdx.x] = s;
        __threadfence();
        unsigned ticket = atomicAdd(&g_count, 1u);
        *islast_p = (ticket == (unsigned)(gridDim.x - 1)) ? 1 : 0;
    }
    __syncthreads();

    // ---- last block folds partials (deterministic fixed tree) ----
    if (*islast_p) {
        double s = 0.0;
        for (int i = threadIdx.x; i < NBLK; i += 256)
            s += *((volatile double*)&g_partial[i]);
        red[threadIdx.x] = s;
        __syncthreads();
#pragma unroll
        for (int o = 128; o > 0; o >>= 1) {
            if (threadIdx.x < o) red[threadIdx.x] += red[threadIdx.x + o];
            __syncthreads();
        }
        if (threadIdx.x == 0) {
            out[0] = (float)(red[0] / (double)B);
            g_count = 0;  // reset for next graph replay
        }
    }
}

extern "C" void kernel_launch(void* const* d_in, const int* in_sizes, int n_in,
                              void* d_out, int out_size) {
    const float* pred      = (const float*)d_in[0];
    const int*   label_rc  = (const int*)d_in[1];
    const float* label_box = (const float*)d_in[2];
    float* out = (float*)d_out;

    int B = in_sizes[0] / SLAB_FLOATS;  // pred is [B, 8, 8, 8]
    size_t smem = (size_t)WPB * SLAB_FLOATS * sizeof(float);  // 16 KB

    yolo_loss_kernel<<<NBLK, WPB * 32, smem>>>(pred, label_rc, label_box, B, out);
}

// round 7
// speedup vs baseline: 1.0618x; 1.0618x over previous
#include <cuda_runtime.h>
#include <cuda_bf16.h>
#include <cstdint>

#define LAMBDA_COORD 5.0f
#define LAMBDA_NOOBJ 0.5f
#define EPS 1e-9f
#define WPB 8                 // warps per block
#define BPSM 4                // blocks per SM
#define NBLK (148 * BPSM)     // one resident wave = 592 blocks
#define SLAB_FLOATS 512       // 8*8*8 floats per batch

__device__ double g_partial[NBLK];
__device__ unsigned g_count = 0;

__device__ __forceinline__ float bbox_iou(float px, float py, float pr,
                                          float gx, float gy, float gr) {
    float l1 = px - pr, r1 = px + pr, t1 = py - pr, b1 = py + pr;
    float l2 = gx - gr, r2 = gx + gr, t2 = gy - gr, b2 = gy + gr;
    float iw = fmaxf(fminf(r1, r2) - fmaxf(l1, l2), 0.0f);
    float ih = fmaxf(fminf(b1, b2) - fmaxf(t1, t2), 0.0f);
    float inter = iw * ih;
    float a1 = (r1 - l1) * (b1 - t1);
    float a2 = (r2 - l2) * (b2 - t2);
    return inter / (a1 + a2 - inter + EPS);
}

__global__ void __launch_bounds__(WPB * 32, BPSM)
yolo_loss_kernel(const float* __restrict__ pred,
                 const int*   __restrict__ label_rc,
                 const float* __restrict__ label_box,
                 int B, float* __restrict__ out) {
    // Dynamic smem: WPB * 2KB stash regions = 16 KB. No static shared;
    // the post-loop reduction aliases into this buffer.
    extern __shared__ float dsh[];

    const int warp = threadIdx.x >> 5;
    const int lane = threadIdx.x & 31;
    const int NW = NBLK * WPB;
    const int b0 = blockIdx.x * WPB + warp;

    float4* shw4 = reinterpret_cast<float4*>(dsh + warp * SLAB_FLOATS);

    float acc  = 0.0f;   // coord + conf losses (already weighted)
    float nsum = 0.0f;   // sum of c3^2 + c7^2 over ALL cells (unweighted)
    float nsub = 0.0f;   // sum over distinct object cells (unweighted)

    // ---- prefetch first batch: pred slab to regs + labels ----
    float4 c0, c1, c2, c3;
    if (b0 < B) {
        const float4* p4 = reinterpret_cast<const float4*>(pred + (size_t)b0 * SLAB_FLOATS);
        c0 = p4[lane]; c1 = p4[lane + 32]; c2 = p4[lane + 64]; c3 = p4[lane + 96];
    }
    int2 nrc = make_int2(0, 0);
    float ngx = 0.f, ngy = 0.f, ngr = 0.f;
    if (lane < 16 && b0 < B) {
        nrc = reinterpret_cast<const int2*>(label_rc)[(size_t)b0 * 16 + lane];
        const float* bx = label_box + ((size_t)b0 * 16 + lane) * 3;
        ngx = bx[0]; ngy = bx[1]; ngr = bx[2];
    }

    for (int b = b0; b < B; b += NW) {
        const int bn = b + NW;

        // ---- issue next batch's global loads (independent chain) ----
        float4 n0, n1, n2, n3;
        if (bn < B) {
            const float4* p4 = reinterpret_cast<const float4*>(pred + (size_t)bn * SLAB_FLOATS);
            n0 = p4[lane]; n1 = p4[lane + 32]; n2 = p4[lane + 64]; n3 = p4[lane + 96];
        }

        int2 rc = nrc;
        float gx = ngx, gy = ngy, gr = ngr;

        // prefetch next batch's labels
        if (lane < 16 && bn < B) {
            nrc = reinterpret_cast<const int2*>(label_rc)[(size_t)bn * 16 + lane];
            const float* bx = label_box + ((size_t)bn * 16 + lane) * 3;
            ngx = bx[0]; ngy = bx[1]; ngr = bx[2];
        }

        // ---- stash slab (unconditional) + noobj total sum (unconditional) ----
        shw4[lane]      = c0;
        shw4[lane + 32] = c1;
        shw4[lane + 64] = c2;
        shw4[lane + 96] = c3;
        nsum = fmaf(c0.w, c0.w, nsum);
        nsum = fmaf(c1.w, c1.w, nsum);
        nsum = fmaf(c2.w, c2.w, nsum);
        nsum = fmaf(c3.w, c3.w, nsum);
        __syncwarp();

        // ---- dedupe object cells: leader = lowest lane with this cell ----
        int cell = (lane < 16) ? (rc.x * 8 + rc.y) : (64 + lane);  // >=16: unique dummies
        unsigned peers = __match_any_sync(0xffffffffu, cell);
        bool leader = (lane == (__ffs(peers) - 1));

        // ---- per-label coord + conf losses (lanes 0..15) ----
        if (lane < 16) {
            float4 a = shw4[cell * 2];       // p0..p3
            float4 c = shw4[cell * 2 + 1];   // q0..q3

            float iou1 = bbox_iou(a.x, a.y, a.z, gx, gy, gr);
            float iou2 = bbox_iou(c.x, c.y, c.z, gx, gy, gr);
            bool swp = iou2 > iou1;

            float cx   = swp ? c.x : a.x;
            float cy   = swp ? c.y : a.y;
            float cr   = swp ? c.z : a.z;
            float conf = swp ? c.w : a.w;
            float ucnf = swp ? a.w : c.w;
            float big  = swp ? iou2 : iou1;
            float sml  = swp ? iou1 : iou2;

            float dx = cx - gx, dy = cy - gy, dr = cr - gr;
            acc += LAMBDA_COORD * (dx * dx + dy * dy + dr * dr);
            float dc = big - conf;
            acc += dc * dc;
            float du = sml - ucnf;
            acc += LAMBDA_NOOBJ * du * du;

            // subtract this (distinct) object cell from the noobj total
            if (leader) {
                nsub = fmaf(a.w, a.w, nsub);
                nsub = fmaf(c.w, c.w, nsub);
            }
        }
        __syncwarp();  // protect smem stash before next iteration's stores

        c0 = n0; c1 = n1; c2 = n2; c3 = n3;
    }

    // combine: noobj = LAMBDA_NOOBJ * (nsum - nsub)
    acc += LAMBDA_NOOBJ * (nsum - nsub);

    __syncthreads();  // all warps done before aliasing dsh as reduction scratch

    double* blocksum = reinterpret_cast<double*>(dsh);        // 8 doubles
    int*    islast_p = reinterpret_cast<int*>(dsh + 16);      // 1 int
    double* red      = reinterpret_cast<double*>(dsh + 32);   // 256 doubles

    // warp reduce
#pragma unroll
    for (int o = 16; o > 0; o >>= 1)
        acc += __shfl_xor_sync(0xffffffffu, acc, o);
    if (lane == 0) blocksum[warp] = (double)acc;
    __syncthreads();

    if (threadIdx.x == 0) {
        double s = 0.0;
#pragma unroll
        for (int w = 0; w < WPB; w++) s += blocksum[w];
        g_partial[blockIdx.x] = s;
        __threadfence();
        unsigned ticket = atomicAdd(&g_count, 1u);
        *islast_p = (ticket == (unsigned)(gridDim.x - 1)) ? 1 : 0;
    }
    __syncthreads();

    // ---- last block folds partials (deterministic fixed tree) ----
    if (*islast_p) {
        double s = 0.0;
        for (int i = threadIdx.x; i < NBLK; i += 256)
            s += *((volatile double*)&g_partial[i]);
        red[threadIdx.x] = s;
        __syncthreads();
#pragma unroll
        for (int o = 128; o > 0; o >>= 1) {
            if (threadIdx.x < o) red[threadIdx.x] += red[threadIdx.x + o];
            __syncthreads();
        }
        if (threadIdx.x == 0) {
            out[0] = (float)(red[0] / (double)B);
            g_count = 0;  // reset for next graph replay
        }
    }
}

extern "C" void kernel_launch(void* const* d_in, const int* in_sizes, int n_in,
                              void* d_out, int out_size) {
    const float* pred      = (const float*)d_in[0];
    const int*   label_rc  = (const int*)d_in[1];
    const float* label_box = (const float*)d_in[2];
    float* out = (float*)d_out;

    int B = in_sizes[0] / SLAB_FLOATS;  // pred is [B, 8, 8, 8]
    size_t smem = (size_t)WPB * SLAB_FLOATS * sizeof(float);  // 16 KB

    yolo_loss_kernel<<<NBLK, WPB * 32, smem>>>(pred, label_rc, label_box, B, out);
}

// round 8
// speedup vs baseline: 1.2793x; 1.2048x over previous
#include <cuda_runtime.h>
#include <cuda_bf16.h>
#include <cstdint>

#define LAMBDA_COORD 5.0f
#define LAMBDA_NOOBJ 0.5f
#define EPS 1e-9f
#define WPB 8                 // warps per block
#define BPSM 2                // blocks per SM (reg budget 128)
#define NBLK (148 * BPSM)     // one resident wave = 296 blocks
#define SLAB_FLOATS 512       // 8*8*8 floats per batch

__device__ double g_partial[NBLK];
__device__ unsigned g_count = 0;

__device__ __forceinline__ float bbox_iou(float px, float py, float pr,
                                          float gx, float gy, float gr) {
    float l1 = px - pr, r1 = px + pr, t1 = py - pr, b1 = py + pr;
    float l2 = gx - gr, r2 = gx + gr, t2 = gy - gr, b2 = gy + gr;
    float iw = fmaxf(fminf(r1, r2) - fmaxf(l1, l2), 0.0f);
    float ih = fmaxf(fminf(b1, b2) - fmaxf(t1, t2), 0.0f);
    float inter = iw * ih;
    float a1 = (r1 - l1) * (b1 - t1);
    float a2 = (r2 - l2) * (b2 - t2);
    return inter / (a1 + a2 - inter + EPS);
}

__global__ void __launch_bounds__(WPB * 32, BPSM)
yolo_loss_kernel(const float* __restrict__ pred,
                 const int*   __restrict__ label_rc,
                 const float* __restrict__ label_box,
                 int B, float* __restrict__ out) {
    // Dynamic smem: WPB * 4KB (two slabs per warp) = 32 KB. No static shared;
    // the post-loop reduction aliases into this buffer.
    extern __shared__ float dsh[];

    const int warp = threadIdx.x >> 5;
    const int lane = threadIdx.x & 31;
    const int TW = NBLK * WPB;           // total warps
    const int P = (B + 1) >> 1;          // batch pairs
    const int p0 = blockIdx.x * WPB + warp;

    const int li   = lane & 15;          // label index within batch
    const int half = lane >> 4;          // 0 = batch A, 1 = batch B

    float4* bufA = reinterpret_cast<float4*>(dsh) + warp * 256;
    float4* bufB = bufA + 128;

    float acc  = 0.0f;   // coord + conf (weighted)
    float nsum = 0.0f;   // c3^2+c7^2 over ALL cells
    float nsub = 0.0f;   // over distinct object cells

    // ---- prefetch first pair: 2 slabs (8 f4) + labels ----
    float4 a0, a1, a2, a3, e0, e1, e2, e3;
    a0 = a1 = a2 = a3 = e0 = e1 = e2 = e3 = make_float4(0.f, 0.f, 0.f, 0.f);
    if (p0 < P) {
        const float4* pa = reinterpret_cast<const float4*>(pred + (size_t)p0 * 1024);
        a0 = __ldcs(pa + lane);       a1 = __ldcs(pa + lane + 32);
        a2 = __ldcs(pa + lane + 64);  a3 = __ldcs(pa + lane + 96);
        if (2 * p0 + 1 < B) {
            e0 = __ldcs(pa + lane + 128); e1 = __ldcs(pa + lane + 160);
            e2 = __ldcs(pa + lane + 192); e3 = __ldcs(pa + lane + 224);
        }
    }
    int2 nrc = make_int2(0, 0);
    float ngx = 0.f, ngy = 0.f, ngr = 0.f;
    bool nval = false;
    if (p0 < P) {
        int bb = 2 * p0 + half;
        if (bb < B) {
            nval = true;
            nrc = reinterpret_cast<const int2*>(label_rc)[(size_t)bb * 16 + li];
            const float* bx = label_box + ((size_t)bb * 16 + li) * 3;
            ngx = bx[0]; ngy = bx[1]; ngr = bx[2];
        }
    }

    for (int p = p0; p < P; p += TW) {
        const int pn = p + TW;

        // ---- issue next pair's 8 global loads (independent chain) ----
        float4 x0, x1, x2, x3, y0, y1, y2, y3;
        x0 = x1 = x2 = x3 = y0 = y1 = y2 = y3 = make_float4(0.f, 0.f, 0.f, 0.f);
        if (pn < P) {
            const float4* pa = reinterpret_cast<const float4*>(pred + (size_t)pn * 1024);
            x0 = __ldcs(pa + lane);       x1 = __ldcs(pa + lane + 32);
            x2 = __ldcs(pa + lane + 64);  x3 = __ldcs(pa + lane + 96);
            if (2 * pn + 1 < B) {
                y0 = __ldcs(pa + lane + 128); y1 = __ldcs(pa + lane + 160);
                y2 = __ldcs(pa + lane + 192); y3 = __ldcs(pa + lane + 224);
            }
        }

        // current labels
        int2 rc = nrc;
        float gx = ngx, gy = ngy, gr = ngr;
        bool valid = nval;

        // prefetch next pair's labels
        nval = false;
        nrc = make_int2(0, 0);
        if (pn < P) {
            int bb = 2 * pn + half;
            if (bb < B) {
                nval = true;
                nrc = reinterpret_cast<const int2*>(label_rc)[(size_t)bb * 16 + li];
                const float* bx = label_box + ((size_t)bb * 16 + li) * 3;
                ngx = bx[0]; ngy = bx[1]; ngr = bx[2];
            }
        }

        // ---- stash both slabs + unconditional noobj totals ----
        bufA[lane] = a0; bufA[lane + 32] = a1; bufA[lane + 64] = a2; bufA[lane + 96] = a3;
        bufB[lane] = e0; bufB[lane + 32] = e1; bufB[lane + 64] = e2; bufB[lane + 96] = e3;
        nsum = fmaf(a0.w, a0.w, nsum); nsum = fmaf(a1.w, a1.w, nsum);
        nsum = fmaf(a2.w, a2.w, nsum); nsum = fmaf(a3.w, a3.w, nsum);
        nsum = fmaf(e0.w, e0.w, nsum); nsum = fmaf(e1.w, e1.w, nsum);
        nsum = fmaf(e2.w, e2.w, nsum); nsum = fmaf(e3.w, e3.w, nsum);
        __syncwarp();

        // ---- full-warp label section: A on lanes 0-15, B on lanes 16-31 ----
        int cell = valid ? (rc.x * 8 + rc.y) : 0;           // 0..63
        int enc  = valid ? (cell + (half << 6)) : (128 + lane);  // distinct per batch
        unsigned peers = __match_any_sync(0xffffffffu, enc);
        bool leader = (lane == (__ffs(peers) - 1));

        const float4* src = half ? bufB : bufA;
        float4 A = src[cell * 2];
        float4 C = src[cell * 2 + 1];

        float iou1 = bbox_iou(A.x, A.y, A.z, gx, gy, gr);
        float iou2 = bbox_iou(C.x, C.y, C.z, gx, gy, gr);
        bool swp = iou2 > iou1;

        float cx   = swp ? C.x : A.x;
        float cy   = swp ? C.y : A.y;
        float cr   = swp ? C.z : A.z;
        float conf = swp ? C.w : A.w;
        float ucnf = swp ? A.w : C.w;
        float big  = swp ? iou2 : iou1;
        float sml  = swp ? iou1 : iou2;

        if (valid) {
            float dx = cx - gx, dy = cy - gy, dr = cr - gr;
            acc += LAMBDA_COORD * (dx * dx + dy * dy + dr * dr);
            float dc = big - conf;
            acc += dc * dc;
            float du = sml - ucnf;
            acc += LAMBDA_NOOBJ * du * du;
            if (leader) {       // distinct object cell: remove from noobj total
                nsub = fmaf(A.w, A.w, nsub);
                nsub = fmaf(C.w, C.w, nsub);
            }
        }
        __syncwarp();  // protect smem stash before next iteration's stores

        a0 = x0; a1 = x1; a2 = x2; a3 = x3;
        e0 = y0; e1 = y1; e2 = y2; e3 = y3;
    }

    acc += LAMBDA_NOOBJ * (nsum - nsub);

    __syncthreads();  // all warps done before aliasing dsh as reduction scratch

    double* blocksum = reinterpret_cast<double*>(dsh);        // 8 doubles
    int*    islast_p = reinterpret_cast<int*>(dsh + 16);      // 1 int
    double* red      = reinterpret_cast<double*>(dsh + 32);   // 256 doubles

    // warp reduce
#pragma unroll
    for (int o = 16; o > 0; o >>= 1)
        acc += __shfl_xor_sync(0xffffffffu, acc, o);
    if (lane == 0) blocksum[warp] = (double)acc;
    __syncthreads();

    if (threadIdx.x == 0) {
        double s = 0.0;
#pragma unroll
        for (int w = 0; w < WPB; w++) s += blocksum[w];
        g_partial[blockIdx.x] = s;
        __threadfence();
        unsigned ticket = atomicAdd(&g_count, 1u);
        *islast_p = (ticket == (unsigned)(gridDim.x - 1)) ? 1 : 0;
    }
    __syncthreads();

    // ---- last block folds partials (deterministic fixed tree) ----
    if (*islast_p) {
        double s = 0.0;
        for (int i = threadIdx.x; i < NBLK; i += 256)
            s += *((volatile double*)&g_partial[i]);
        red[threadIdx.x] = s;
        __syncthreads();
#pragma unroll
        for (int o = 128; o > 0; o >>= 1) {
            if (threadIdx.x < o) red[threadIdx.x] += red[threadIdx.x + o];
            __syncthreads();
        }
        if (threadIdx.x == 0) {
            out[0] = (float)(red[0] / (double)B);
            g_count = 0;  // reset for next graph replay
        }
    }
}

extern "C" void kernel_launch(void* const* d_in, const int* in_sizes, int n_in,
                              void* d_out, int out_size) {
    const float* pred      = (const float*)d_in[0];
    const int*   label_rc  = (const int*)d_in[1];
    const float* label_box = (const float*)d_in[2];
    float* out = (float*)d_out;

    int B = in_sizes[0] / SLAB_FLOATS;  // pred is [B, 8, 8, 8]
    size_t smem = (size_t)WPB * 2 * SLAB_FLOATS * sizeof(float);  // 32 KB

    yolo_loss_kernel<<<NBLK, WPB * 32, smem>>>(pred, label_rc, label_box, B, out);
}